// round 1
// baseline (speedup 1.0000x reference)
#include <cuda_runtime.h>
#include <math.h>

#define NSUB   64
#define HID1   10
#define HID2   6
#define GRIDN  101
#define TABN   896
#define XLO    (-8.0f)
#define TAB_H  (16.0f/895.0f)
#define INV_H  (895.0f/16.0f)
#define TAB_WORDS (TABN*NSUB)
#define TAB_BYTES (TAB_WORDS*4)

// Scratch (no allocations allowed in kernel_launch)
__device__ float g_table[TAB_WORDS];
__device__ float g_mean[NSUB];
__device__ float g_inv[NSUB];

// Accurate per-subnet MLP evaluation (used only for table/stats build).
__device__ __forceinline__ float mlp_eval(
    float x, int s,
    const float* __restrict__ W1, const float* __restrict__ b1,
    const float* __restrict__ W2, const float* __restrict__ b2,
    const float* __restrict__ W3, const float* __restrict__ b3)
{
    float h1[HID1];
#pragma unroll
    for (int i = 0; i < HID1; i++)
        h1[i] = tanhf(fmaf(x, W1[s*HID1 + i], b1[s*HID1 + i]));
    float out = b3[s];
#pragma unroll
    for (int k = 0; k < HID2; k++) {
        float acc = b2[s*HID2 + k];
#pragma unroll
        for (int i = 0; i < HID1; i++)
            acc = fmaf(h1[i], W2[(s*HID1 + i)*HID2 + k], acc);
        out = fmaf(tanhf(acc), W3[s*HID2 + k], out);
    }
    return out;
}

// One block per subnet: evaluate the 101-point grid, compute mean / 1/std.
__global__ void stats_kernel(
    const float* __restrict__ W1, const float* __restrict__ b1,
    const float* __restrict__ W2, const float* __restrict__ b2,
    const float* __restrict__ W3, const float* __restrict__ b3)
{
    __shared__ float vals[GRIDN];
    const int s = blockIdx.x;
    const int tid = threadIdx.x;
    if (tid < GRIDN) {
        float gx = fmaf((float)tid, 0.02f, -1.0f);   // linspace(-1,1,101)
        vals[tid] = mlp_eval(gx, s, W1, b1, W2, b2, W3, b3);
    }
    __syncthreads();
    if (tid == 0) {
        float sum = 0.0f;
        for (int k = 0; k < GRIDN; k++) sum += vals[k];
        float mean = sum / (float)GRIDN;
        float var = 0.0f;
        for (int k = 0; k < GRIDN; k++) {
            float dv = vals[k] - mean;
            var = fmaf(dv, dv, var);
        }
        var /= (float)GRIDN;                 // population std (ddof=0), as jnp.std
        float norm = fmaxf(sqrtf(var), 1e-10f);
        g_mean[s] = mean;
        g_inv[s]  = 1.0f / norm;
    }
}

// One thread per table entry. Table layout [knot][subnet]: stride 64 words
// => shared-memory bank == subnet % 32 == lane, conflict-free gathers later.
__global__ void fill_kernel(
    const float* __restrict__ W1, const float* __restrict__ b1,
    const float* __restrict__ W2, const float* __restrict__ b2,
    const float* __restrict__ W3, const float* __restrict__ b3)
{
    int gid = blockIdx.x * blockDim.x + threadIdx.x;
    if (gid >= TAB_WORDS) return;
    int s = gid & (NSUB - 1);
    int i = gid >> 6;
    float xi = fmaf((float)i, TAB_H, XLO);
    float v = mlp_eval(xi, s, W1, b1, W2, b2, W3, b3);
    g_table[gid] = (v - g_mean[s]) * g_inv[s];   // fold normalization in
}

// Main kernel: 4-point Lagrange cubic interpolation from shared-memory table.
__global__ __launch_bounds__(1024) void apply_kernel(
    const float* __restrict__ inputs, const int* __restrict__ idx,
    float* __restrict__ out, int total)
{
    extern __shared__ float tab[];
    {   // stage the full table into shared memory (vectorized)
        const float4* src = (const float4*)g_table;
        float4* dst = (float4*)tab;
        for (int i = threadIdx.x; i < TAB_WORDS / 4; i += blockDim.x)
            dst[i] = src[i];
    }
    __syncthreads();

    const int soff = threadIdx.x & (NSUB - 1);   // output/table column (fixed per thread)
    const int d = idx[soff] - soff;              // input-column delta (0 for arange idx)

    auto interp = [&](float x) -> float {
        float t = (x - XLO) * INV_H;
        t = fminf(fmaxf(t, 0.0f), 894.99f);
        int i = (int)t;
        i = max(1, min(i, TABN - 3));
        float fr = t - (float)i;
        int base = ((i - 1) << 6) + soff;
        float f0 = tab[base];
        float f1 = tab[base + 64];
        float f2 = tab[base + 128];
        float f3 = tab[base + 192];
        // Lagrange weights for nodes {-1,0,1,2} at position fr in [0,1)
        float a = fr - 1.0f, b = fr - 2.0f, c = fr + 1.0f;
        float w0 = -fr * a * b * (1.0f / 6.0f);
        float w1 =  c  * a * b * 0.5f;
        float w2 = -c  * fr * b * 0.5f;
        float w3 =  c  * fr * a * (1.0f / 6.0f);
        float r = f0 * w0;
        r = fmaf(f1, w1, r);
        r = fmaf(f2, w2, r);
        r = fmaf(f3, w3, r);
        return r;
    };

    const int stride = gridDim.x * blockDim.x;   // multiple of 64 -> soff invariant
    int e = blockIdx.x * blockDim.x + threadIdx.x;

    // 4-way unrolled main loop: batch the global loads for MLP
    for (; e + 3 * stride < total; e += 4 * stride) {
        float x0 = inputs[e + d];
        float x1 = inputs[e + stride + d];
        float x2 = inputs[e + 2 * stride + d];
        float x3 = inputs[e + 3 * stride + d];
        out[e]              = interp(x0);
        out[e + stride]     = interp(x1);
        out[e + 2 * stride] = interp(x2);
        out[e + 3 * stride] = interp(x3);
    }
    for (; e < total; e += stride)
        out[e] = interp(inputs[e + d]);
}

extern "C" void kernel_launch(void* const* d_in, const int* in_sizes, int n_in,
                              void* d_out, int out_size)
{
    const float* inputs = (const float*)d_in[0];
    const int*   idx    = (const int*)d_in[1];
    const float* W1     = (const float*)d_in[2];
    const float* b1     = (const float*)d_in[3];
    const float* W2     = (const float*)d_in[4];
    const float* b2     = (const float*)d_in[5];
    const float* W3     = (const float*)d_in[6];
    const float* b3     = (const float*)d_in[7];
    float* out = (float*)d_out;

    cudaFuncSetAttribute(apply_kernel,
                         cudaFuncAttributeMaxDynamicSharedMemorySize, TAB_BYTES);

    stats_kernel<<<NSUB, 128>>>(W1, b1, W2, b2, W3, b3);
    fill_kernel<<<(TAB_WORDS + 1023) / 1024, 1024>>>(W1, b1, W2, b2, W3, b3);
    apply_kernel<<<148, 1024, TAB_BYTES>>>(inputs, idx, out, out_size);
}

// round 2
// speedup vs baseline: 1.6262x; 1.6262x over previous
#include <cuda_runtime.h>
#include <math.h>

#define NSUB   64
#define HID1   10
#define HID2   6
#define GRIDN  101
#define TABN   384
#define XLO    (-8.0f)
#define TAB_H  (16.0f/383.0f)
#define INV_H  (383.0f/16.0f)
#define TAB_WORDS (TABN*NSUB)
#define TAB_BYTES (TAB_WORDS*4)

// Scratch (no allocations allowed in kernel_launch)
__device__ float g_table[TAB_WORDS];

// ---------------------------------------------------------------------------
// Fused setup: one block per subnet. Computes the 101-point grid stats with a
// warp-shuffle reduction, then fills this subnet's column of the normalized
// lookup table. Weights staged once into shared memory.
// ---------------------------------------------------------------------------
__global__ __launch_bounds__(128) void setup_kernel(
    const float* __restrict__ W1, const float* __restrict__ b1,
    const float* __restrict__ W2, const float* __restrict__ b2,
    const float* __restrict__ W3, const float* __restrict__ b3)
{
    __shared__ float sW1[HID1], sB1[HID1];
    __shared__ float sW2[HID1*HID2], sB2[HID2], sW3[HID2];
    __shared__ float sB3;
    __shared__ float vals[GRIDN];
    __shared__ float s_mean, s_inv;

    const int s = blockIdx.x;
    const int tid = threadIdx.x;

    if (tid < HID1)      { sW1[tid] = W1[s*HID1 + tid]; sB1[tid] = b1[s*HID1 + tid]; }
    if (tid < HID1*HID2)   sW2[tid] = W2[s*HID1*HID2 + tid];
    if (tid < HID2)      { sB2[tid] = b2[s*HID2 + tid]; sW3[tid] = W3[s*HID2 + tid]; }
    if (tid == 0)          sB3 = b3[s];
    __syncthreads();

    auto eval = [&](float x) -> float {
        float h1[HID1];
#pragma unroll
        for (int i = 0; i < HID1; i++)
            h1[i] = tanhf(fmaf(x, sW1[i], sB1[i]));
        float out = sB3;
#pragma unroll
        for (int k = 0; k < HID2; k++) {
            float acc = sB2[k];
#pragma unroll
            for (int i = 0; i < HID1; i++)
                acc = fmaf(h1[i], sW2[i*HID2 + k], acc);
            out = fmaf(tanhf(acc), sW3[k], out);
        }
        return out;
    };

    if (tid < GRIDN)
        vals[tid] = eval(fmaf((float)tid, 0.02f, -1.0f));   // linspace(-1,1,101)
    __syncthreads();

    if (tid < 32) {
        float sum = 0.0f;
        for (int k = tid; k < GRIDN; k += 32) sum += vals[k];
#pragma unroll
        for (int o = 16; o; o >>= 1) sum += __shfl_xor_sync(0xffffffff, sum, o);
        float mean = sum / (float)GRIDN;
        float var = 0.0f;
        for (int k = tid; k < GRIDN; k += 32) {
            float dv = vals[k] - mean;
            var = fmaf(dv, dv, var);
        }
#pragma unroll
        for (int o = 16; o; o >>= 1) var += __shfl_xor_sync(0xffffffff, var, o);
        if (tid == 0) {
            s_mean = mean;                                   // population std (ddof=0)
            s_inv  = 1.0f / fmaxf(sqrtf(var / (float)GRIDN), 1e-10f);
        }
    }
    __syncthreads();

    const float mean = s_mean, inv = s_inv;
    for (int i = tid; i < TABN; i += 128) {
        float xi = fmaf((float)i, TAB_H, XLO);
        g_table[i*NSUB + s] = (eval(xi) - mean) * inv;       // normalization folded in
    }
}

// ---------------------------------------------------------------------------
// Main kernel: 4-point Lagrange cubic interpolation from a shared-memory
// table. Layout [knot][subnet]: word stride 64 => bank == lane, conflict-free.
// ---------------------------------------------------------------------------
__global__ __launch_bounds__(1024) void apply_kernel(
    const float* __restrict__ inputs, const int* __restrict__ idx,
    float* __restrict__ out, int total)
{
    extern __shared__ float tab[];
    {   // stage the table (vectorized, 6 float4 per thread)
        const float4* src = (const float4*)g_table;
        float4* dst = (float4*)tab;
        for (int i = threadIdx.x; i < TAB_WORDS / 4; i += blockDim.x)
            dst[i] = src[i];
    }
    __syncthreads();

    const int soff = threadIdx.x & (NSUB - 1);   // table column, fixed per thread
    const int d = idx[soff] - soff;              // input-column delta (0 for arange)

    auto interp = [&](float x) -> float {
        float t = (x - XLO) * INV_H;
        t = fminf(fmaxf(t, 0.0f), (float)(TABN - 1) - 0.01f);
        int i = (int)t;
        i = max(1, min(i, TABN - 3));
        float fr = t - (float)i;
        int base = ((i - 1) << 6) + soff;
        float f0 = tab[base];
        float f1 = tab[base + 64];
        float f2 = tab[base + 128];
        float f3 = tab[base + 192];
        // Lagrange weights for nodes {-1,0,1,2} at fr in [0,1)
        float a = fr - 1.0f, b = fr - 2.0f, c = fr + 1.0f;
        float w0 = -fr * a * b * (1.0f / 6.0f);
        float w1 =  c  * a * b * 0.5f;
        float w2 = -c  * fr * b * 0.5f;
        float w3 =  c  * fr * a * (1.0f / 6.0f);
        float r = f0 * w0;
        r = fmaf(f1, w1, r);
        r = fmaf(f2, w2, r);
        r = fmaf(f3, w3, r);
        return r;
    };

    const int stride = gridDim.x * blockDim.x;   // multiple of 64 -> soff invariant
    int e = blockIdx.x * blockDim.x + threadIdx.x;

    for (; e + 3 * stride < total; e += 4 * stride) {
        float x0 = inputs[e + d];
        float x1 = inputs[e + stride + d];
        float x2 = inputs[e + 2 * stride + d];
        float x3 = inputs[e + 3 * stride + d];
        out[e]              = interp(x0);
        out[e + stride]     = interp(x1);
        out[e + 2 * stride] = interp(x2);
        out[e + 3 * stride] = interp(x3);
    }
    for (; e < total; e += stride)
        out[e] = interp(inputs[e + d]);
}

extern "C" void kernel_launch(void* const* d_in, const int* in_sizes, int n_in,
                              void* d_out, int out_size)
{
    const float* inputs = (const float*)d_in[0];
    const int*   idx    = (const int*)d_in[1];
    const float* W1     = (const float*)d_in[2];
    const float* b1     = (const float*)d_in[3];
    const float* W2     = (const float*)d_in[4];
    const float* b2     = (const float*)d_in[5];
    const float* W3     = (const float*)d_in[6];
    const float* b3     = (const float*)d_in[7];
    float* out = (float*)d_out;

    cudaFuncSetAttribute(apply_kernel,
                         cudaFuncAttributeMaxDynamicSharedMemorySize, TAB_BYTES);

    setup_kernel<<<NSUB, 128>>>(W1, b1, W2, b2, W3, b3);
    apply_kernel<<<148, 1024, TAB_BYTES>>>(inputs, idx, out, out_size);
}

// round 3
// speedup vs baseline: 1.6355x; 1.0057x over previous
#include <cuda_runtime.h>
#include <math.h>

#define NSUB   64
#define HID1   10
#define HID2   6
#define GRIDN  101
#define TABN   208                  // knots over [-8,8]
#define XLO    (-8.0f)
#define TAB_H  (16.0f/207.0f)
#define INV_H  (207.0f/16.0f)
#define TAB_PAIRS (TABN*NSUB)       // float2 entries
#define TAB_BYTES (TAB_PAIRS*8)     // 106496 B -> 2 blocks/SM fit (213KB < 227KB)

// Scratch (no allocations allowed in kernel_launch)
__device__ float2 g_table[TAB_PAIRS];

// ---------------------------------------------------------------------------
// Fused setup: one block per subnet. Grid stats via warp-shuffle reduction,
// then fill this subnet's pair-packed column: entry i = (f_i, f_{i+1}).
// ---------------------------------------------------------------------------
__global__ __launch_bounds__(256) void setup_kernel(
    const float* __restrict__ W1, const float* __restrict__ b1,
    const float* __restrict__ W2, const float* __restrict__ b2,
    const float* __restrict__ W3, const float* __restrict__ b3)
{
    __shared__ float sW1[HID1], sB1[HID1];
    __shared__ float sW2[HID1*HID2], sB2[HID2], sW3[HID2];
    __shared__ float sB3;
    __shared__ float gvals[GRIDN];
    __shared__ float tvals[TABN + 1];
    __shared__ float s_mean, s_inv;

    const int s = blockIdx.x;
    const int tid = threadIdx.x;

    if (tid < HID1)      { sW1[tid] = W1[s*HID1 + tid]; sB1[tid] = b1[s*HID1 + tid]; }
    if (tid < HID1*HID2)   sW2[tid] = W2[s*HID1*HID2 + tid];
    if (tid < HID2)      { sB2[tid] = b2[s*HID2 + tid]; sW3[tid] = W3[s*HID2 + tid]; }
    if (tid == 0)          sB3 = b3[s];
    __syncthreads();

    auto eval = [&](float x) -> float {
        float h1[HID1];
#pragma unroll
        for (int i = 0; i < HID1; i++)
            h1[i] = tanhf(fmaf(x, sW1[i], sB1[i]));
        float out = sB3;
#pragma unroll
        for (int k = 0; k < HID2; k++) {
            float acc = sB2[k];
#pragma unroll
            for (int i = 0; i < HID1; i++)
                acc = fmaf(h1[i], sW2[i*HID2 + k], acc);
            out = fmaf(tanhf(acc), sW3[k], out);
        }
        return out;
    };

    // grid stats
    if (tid < GRIDN)
        gvals[tid] = eval(fmaf((float)tid, 0.02f, -1.0f));   // linspace(-1,1,101)
    // raw table values (unnormalized), computed concurrently
    for (int i = tid; i < TABN; i += blockDim.x)
        tvals[i] = eval(fmaf((float)i, TAB_H, XLO));
    __syncthreads();

    if (tid < 32) {
        float sum = 0.0f;
        for (int k = tid; k < GRIDN; k += 32) sum += gvals[k];
#pragma unroll
        for (int o = 16; o; o >>= 1) sum += __shfl_xor_sync(0xffffffff, sum, o);
        float mean = sum / (float)GRIDN;
        float var = 0.0f;
        for (int k = tid; k < GRIDN; k += 32) {
            float dv = gvals[k] - mean;
            var = fmaf(dv, dv, var);
        }
#pragma unroll
        for (int o = 16; o; o >>= 1) var += __shfl_xor_sync(0xffffffff, var, o);
        if (tid == 0) {
            s_mean = mean;                                   // population std (ddof=0)
            s_inv  = 1.0f / fmaxf(sqrtf(var / (float)GRIDN), 1e-10f);
            tvals[TABN] = tvals[TABN - 1];                   // dup for last pair
        }
    }
    __syncthreads();

    const float mean = s_mean, inv = s_inv;
    for (int i = tid; i < TABN; i += blockDim.x) {
        float a = (tvals[i]     - mean) * inv;
        float b = (tvals[i + 1] - mean) * inv;
        g_table[i*NSUB + s] = make_float2(a, b);             // normalization folded in
    }
}

// ---------------------------------------------------------------------------
// Main kernel: cubic Lagrange from a pair-packed shared table.
// Entry (i,s) = (f_i, f_{i+1}); cubic fetches pairs at i-1 and i+1:
// two conflict-free LDS.64 per element (lanes access consecutive float2).
// ---------------------------------------------------------------------------
__global__ __launch_bounds__(1024, 2) void apply_kernel(
    const float* __restrict__ inputs, const int* __restrict__ idx,
    float* __restrict__ out, int total)
{
    extern __shared__ float2 tab[];
    {   // stage the table (128-bit vectorized)
        const float4* src = (const float4*)g_table;
        float4* dst = (float4*)tab;
        for (int i = threadIdx.x; i < TAB_PAIRS / 2; i += blockDim.x)
            dst[i] = src[i];
    }
    __syncthreads();

    const int soff = threadIdx.x & (NSUB - 1);   // table column, fixed per thread
    const int d = idx[soff] - soff;              // input-column delta (0 for arange)

    auto interp = [&](float x) -> float {
        float t = fmaf(x, INV_H, -XLO * INV_H);
        t = fminf(fmaxf(t, 1.0f), (float)(TABN - 3) + 0.999f);
        int i = (int)t;                          // in [1, TABN-3], no int clamp
        float fr = t - (float)i;
        int base = (i << 6) + soff;
        float2 lo = tab[base - NSUB];            // (f_{i-1}, f_i)
        float2 hi = tab[base + NSUB];            // (f_{i+1}, f_{i+2})
        // Lagrange weights for nodes {-1,0,1,2} at fr in [0,1)
        float a = fr - 1.0f, b = fr - 2.0f, c = fr + 1.0f;
        float w0 = -fr * a * b * (1.0f / 6.0f);
        float w1 =  c  * a * b * 0.5f;
        float w2 = -c  * fr * b * 0.5f;
        float w3 =  c  * fr * a * (1.0f / 6.0f);
        float r = lo.x * w0;
        r = fmaf(lo.y, w1, r);
        r = fmaf(hi.x, w2, r);
        r = fmaf(hi.y, w3, r);
        return r;
    };

    const int stride = gridDim.x * blockDim.x;   // multiple of 64 -> soff invariant
    int e = blockIdx.x * blockDim.x + threadIdx.x;

    for (; e + 3 * stride < total; e += 4 * stride) {
        float x0 = inputs[e + d];
        float x1 = inputs[e + stride + d];
        float x2 = inputs[e + 2 * stride + d];
        float x3 = inputs[e + 3 * stride + d];
        out[e]              = interp(x0);
        out[e + stride]     = interp(x1);
        out[e + 2 * stride] = interp(x2);
        out[e + 3 * stride] = interp(x3);
    }
    for (; e < total; e += stride)
        out[e] = interp(inputs[e + d]);
}

extern "C" void kernel_launch(void* const* d_in, const int* in_sizes, int n_in,
                              void* d_out, int out_size)
{
    const float* inputs = (const float*)d_in[0];
    const int*   idx    = (const int*)d_in[1];
    const float* W1     = (const float*)d_in[2];
    const float* b1     = (const float*)d_in[3];
    const float* W2     = (const float*)d_in[4];
    const float* b2     = (const float*)d_in[5];
    const float* W3     = (const float*)d_in[6];
    const float* b3     = (const float*)d_in[7];
    float* out = (float*)d_out;

    cudaFuncSetAttribute(apply_kernel,
                         cudaFuncAttributeMaxDynamicSharedMemorySize, TAB_BYTES);

    setup_kernel<<<NSUB, 256>>>(W1, b1, W2, b2, W3, b3);
    apply_kernel<<<296, 1024, TAB_BYTES>>>(inputs, idx, out, out_size);
}

// round 4
// speedup vs baseline: 1.9121x; 1.1692x over previous
#include <cuda_runtime.h>
#include <math.h>

#define NSUB   64
#define HID1   10
#define HID2   6
#define GRIDN  101
#define NCELL  110                      // cubic cells over [XLO, XHI]
#define NKNOT  (NCELL + 3)              // knots, one extra on each side
#define XLO    (-8.0f)
#define CELL_H (16.0f / (float)NCELL)
#define INV_H  ((float)NCELL / 16.0f)
#define TAB_ENTRIES (NCELL * NSUB)
#define TAB_BYTES   (TAB_ENTRIES * 16)  // 112640 B -> 2 blocks/SM (225 KB)

// Scratch (no allocations allowed in kernel_launch)
__device__ float4 g_table[TAB_ENTRIES];

// ---------------------------------------------------------------------------
// Fused setup: one block per subnet. Grid stats via warp-shuffle reduction,
// then per-cell cubic coefficients (Lagrange through knots c-1..c+2, with
// normalization folded in): p(fr) = c0 + fr*(c1 + fr*(c2 + fr*c3)).
// ---------------------------------------------------------------------------
__global__ __launch_bounds__(128) void setup_kernel(
    const float* __restrict__ W1, const float* __restrict__ b1,
    const float* __restrict__ W2, const float* __restrict__ b2,
    const float* __restrict__ W3, const float* __restrict__ b3)
{
    __shared__ float sW1[HID1], sB1[HID1];
    __shared__ float sW2[HID1*HID2], sB2[HID2], sW3[HID2];
    __shared__ float sB3;
    __shared__ float gvals[GRIDN];
    __shared__ float kn[NKNOT];
    __shared__ float s_mean, s_inv;

    const int s = blockIdx.x;
    const int tid = threadIdx.x;

    if (tid < HID1)      { sW1[tid] = W1[s*HID1 + tid]; sB1[tid] = b1[s*HID1 + tid]; }
    if (tid < HID1*HID2)   sW2[tid] = W2[s*HID1*HID2 + tid];
    if (tid < HID2)      { sB2[tid] = b2[s*HID2 + tid]; sW3[tid] = W3[s*HID2 + tid]; }
    if (tid == 0)          sB3 = b3[s];
    __syncthreads();

    auto eval = [&](float x) -> float {
        float h1[HID1];
#pragma unroll
        for (int i = 0; i < HID1; i++)
            h1[i] = tanhf(fmaf(x, sW1[i], sB1[i]));
        float out = sB3;
#pragma unroll
        for (int k = 0; k < HID2; k++) {
            float acc = sB2[k];
#pragma unroll
            for (int i = 0; i < HID1; i++)
                acc = fmaf(h1[i], sW2[i*HID2 + k], acc);
            out = fmaf(tanhf(acc), sW3[k], out);
        }
        return out;
    };

    if (tid < GRIDN)
        gvals[tid] = eval(fmaf((float)tid, 0.02f, -1.0f));   // linspace(-1,1,101)
    // knot k sits at XLO + (k-1)*h  (one ghost knot each side)
    for (int k = tid; k < NKNOT; k += blockDim.x)
        kn[k] = eval(fmaf((float)(k - 1), CELL_H, XLO));
    __syncthreads();

    if (tid < 32) {
        float sum = 0.0f;
        for (int k = tid; k < GRIDN; k += 32) sum += gvals[k];
#pragma unroll
        for (int o = 16; o; o >>= 1) sum += __shfl_xor_sync(0xffffffff, sum, o);
        float mean = sum / (float)GRIDN;
        float var = 0.0f;
        for (int k = tid; k < GRIDN; k += 32) {
            float dv = gvals[k] - mean;
            var = fmaf(dv, dv, var);
        }
#pragma unroll
        for (int o = 16; o; o >>= 1) var += __shfl_xor_sync(0xffffffff, var, o);
        if (tid == 0) {
            s_mean = mean;                                   // population std (ddof=0)
            s_inv  = 1.0f / fmaxf(sqrtf(var / (float)GRIDN), 1e-10f);
        }
    }
    __syncthreads();

    const float mean = s_mean, inv = s_inv;
    for (int c = tid; c < NCELL; c += blockDim.x) {
        float f0 = (kn[c]     - mean) * inv;
        float f1 = (kn[c + 1] - mean) * inv;
        float f2 = (kn[c + 2] - mean) * inv;
        float f3 = (kn[c + 3] - mean) * inv;
        float c3 = (f3 - 3.0f*f2 + 3.0f*f1 - f0) * (1.0f/6.0f);
        float c2 = (f0 - 2.0f*f1 + f2) * 0.5f;
        float c1 = f2 - f1 - c2 - c3;
        g_table[c*NSUB + s] = make_float4(f1, c1, c2, c3);
    }
}

// ---------------------------------------------------------------------------
// Main kernel: per-cell cubic coefficients from shared memory.
// Per element: LDG + FFMA + 2 clamp + F2I/I2F/FADD + 1 LDS.128 + 3 FFMA + STG.
// Layout [cell][subnet], col == lane => conflict-free LDS.128 phases.
// ---------------------------------------------------------------------------
__global__ __launch_bounds__(1024, 2) void apply_kernel(
    const float* __restrict__ inputs, const int* __restrict__ idx,
    float* __restrict__ out, int total)
{
    extern __shared__ float4 tab[];
    {   // stage table: 112640 B, 128-bit copies
        const float4* src = g_table;
        for (int i = threadIdx.x; i < TAB_ENTRIES; i += blockDim.x)
            tab[i] = src[i];
    }
    __syncthreads();

    const int soff = threadIdx.x & (NSUB - 1);      // table column, fixed per thread
    const float4* col = tab + soff;                  // one IMAD per access below
    const int d = idx[soff] - soff;                  // input-column delta (0 for arange)

    auto interp = [&](float x) -> float {
        float t = fmaf(x, INV_H, -XLO * INV_H);
        t = fminf(fmaxf(t, 0.0f), (float)NCELL - 0.001f);
        int c = (int)t;
        float fr = t - (float)c;
        float4 k = col[c * NSUB];                    // (c0,c1,c2,c3)
        return fmaf(fmaf(fmaf(k.w, fr, k.z), fr, k.y), fr, k.x);
    };

    const int stride = gridDim.x * blockDim.x;       // multiple of 64 -> soff invariant
    int e = blockIdx.x * blockDim.x + threadIdx.x;

    for (; e + 3 * stride < total; e += 4 * stride) {
        float x0 = inputs[e + d];
        float x1 = inputs[e + stride + d];
        float x2 = inputs[e + 2 * stride + d];
        float x3 = inputs[e + 3 * stride + d];
        out[e]              = interp(x0);
        out[e + stride]     = interp(x1);
        out[e + 2 * stride] = interp(x2);
        out[e + 3 * stride] = interp(x3);
    }
    for (; e < total; e += stride)
        out[e] = interp(inputs[e + d]);
}

extern "C" void kernel_launch(void* const* d_in, const int* in_sizes, int n_in,
                              void* d_out, int out_size)
{
    const float* inputs = (const float*)d_in[0];
    const int*   idx    = (const int*)d_in[1];
    const float* W1     = (const float*)d_in[2];
    const float* b1     = (const float*)d_in[3];
    const float* W2     = (const float*)d_in[4];
    const float* b2     = (const float*)d_in[5];
    const float* W3     = (const float*)d_in[6];
    const float* b3     = (const float*)d_in[7];
    float* out = (float*)d_out;

    cudaFuncSetAttribute(apply_kernel,
                         cudaFuncAttributeMaxDynamicSharedMemorySize, TAB_BYTES);

    setup_kernel<<<NSUB, 128>>>(W1, b1, W2, b2, W3, b3);
    apply_kernel<<<296, 1024, TAB_BYTES>>>(inputs, idx, out, out_size);
}